// round 9
// baseline (speedup 1.0000x reference)
#include <cuda_runtime.h>
#include <cuda_bf16.h>
#include <cstddef>

// Problem constants
#define B 32
#define N 2048
#define D 1024
#define H 16
#define HD 64
#define SCALE 0.125f   // 1/sqrt(64)

// ---------------- scratch (device globals; no allocation allowed) -----------
__device__ float g_q[D];                 // q = query @ w_q.T + b_q
__device__ float g_u[H * D];             // u[h,i] = scale * sum_{j in head h} q[j]*w_k[j,i]
__device__ float g_c[H];                 // scale * q_h . b_k_h
__device__ int   g_force[B];             // 1 if row b has no valid key -> force n=0 valid
__device__ unsigned char g_maskb[B * N]; // canonicalized mask (1 = valid)
__device__ float g_probs[B * H * N];     // scores, then softmax probs (in place)
__device__ float g_ctx[B * H * D];       // ctx[b,h,:] = sum_n attn * z
__device__ float g_pooled[B * D];

__device__ __forceinline__ float warp_sum(float v) {
    #pragma unroll
    for (int o = 16; o; o >>= 1) v += __shfl_xor_sync(0xffffffffu, v, o);
    return v;
}

// ---------------- K0: mask dtype detection + canonicalization + force -------
// The wire format of the bool mask is unknown (bool bytes / int32 / float32 /
// bf16). Detect it from bit patterns over the first 16384 words (64 KB is
// within-bounds for every candidate layout), canonicalize into g_maskb as
// uint8, then compute per-batch "all false" force flags. Single block.
__global__ void k_maskprep(const void* __restrict__ mraw) {
    const unsigned int*   wrd = (const unsigned int*)mraw;
    const unsigned short* hlf = (const unsigned short*)mraw;
    const unsigned char*  byt = (const unsigned char*)mraw;

    __shared__ int bad_f32, bad_bf16, bad_i32, mode;
    int t = threadIdx.x;
    if (t == 0) { bad_f32 = 0; bad_bf16 = 0; bad_i32 = 0; }
    __syncthreads();

    int bf = 0, bb = 0, bi = 0;
    for (int i = t; i < (B * N) / 4; i += 1024) {   // 16384 words, safe for all dtypes
        unsigned int x = wrd[i];
        if (x != 0u && x != 0x3F800000u) bf = 1;
        unsigned int lo = x & 0xFFFFu, hi = x >> 16;
        if ((lo != 0u && lo != 0x3F80u) || (hi != 0u && hi != 0x3F80u)) bb = 1;
        if (x > 1u) bi = 1;
    }
    if (bf) bad_f32 = 1;
    if (bb) bad_bf16 = 1;
    if (bi) bad_i32 = 1;
    __syncthreads();
    if (t == 0) mode = !bad_f32 ? 0 : (!bad_bf16 ? 1 : (!bad_i32 ? 2 : 3));
    __syncthreads();

    int m = mode;
    for (int i = t; i < B * N; i += 1024) {
        unsigned char v;
        if      (m == 0) v = (wrd[i] != 0u);   // float32 0.0 / 1.0
        else if (m == 1) v = (hlf[i] != 0);    // bf16
        else if (m == 2) v = (wrd[i] != 0u);   // int32
        else             v = (byt[i] != 0);    // bool bytes
        g_maskb[i] = v;
    }
    __syncthreads();

    // force flags: warp w handles batch w (1024 threads = 32 warps = B)
    int w = t >> 5, lane = t & 31;
    int found = 0;
    for (int n = lane; n < N; n += 32) found |= g_maskb[w * N + n];
    found = __ballot_sync(0xffffffffu, found);
    if (lane == 0) g_force[w] = (found == 0);
}

// ---------------- K1: q[j] = query . w_q[j,:] + b_q[j] ----------------------
__global__ void k_q(const float* __restrict__ query, const float* __restrict__ w_q,
                    const float* __restrict__ b_q) {
    int j    = (blockIdx.x * blockDim.x + threadIdx.x) >> 5;  // one warp per output
    int lane = threadIdx.x & 31;
    if (j >= D) return;
    float acc = 0.f;
    const float* wr = w_q + (size_t)j * D;
    for (int i = lane; i < D; i += 32) acc = fmaf(query[i], wr[i], acc);
    acc = warp_sum(acc);
    if (lane == 0) g_q[j] = acc + b_q[j];
}

// ---------------- K2: u[h,i] (pre-scaled) -----------------------------------
__global__ void k_u(const float* __restrict__ w_k) {
    int t = blockIdx.x * 256 + threadIdx.x;   // 16384 threads
    int h = t >> 10;
    int i = t & (D - 1);
    float acc = 0.f;
    #pragma unroll 8
    for (int j = 0; j < HD; j++)
        acc = fmaf(g_q[h * HD + j], w_k[(size_t)(h * HD + j) * D + i], acc);
    g_u[t] = acc * SCALE;
}

// ---------------- K2c: c[h] = scale * q_h . b_k_h ---------------------------
__global__ void k_c(const float* __restrict__ b_k) {
    int h = threadIdx.x >> 5;
    int lane = threadIdx.x & 31;
    float acc = 0.f;
    for (int j = lane; j < HD; j += 32)
        acc = fmaf(g_q[h * HD + j], b_k[h * HD + j], acc);
    acc = warp_sum(acc);
    if (lane == 0) g_c[h] = acc * SCALE;
}

// ---------------- K3: scores + mask -----------------------------------------
// block = 256 threads = 16 rows x 16 heads (tid = n_local*16 + h).
// u cached in dynamic smem, row stride 1028 floats.
// z read as float4: 16 heads share each address -> coalesced broadcast,
// z streamed from HBM exactly once.
extern "C" __global__ void k_scores(const float* __restrict__ z) {
    extern __shared__ float us[];   // [16][1028]
    for (int idx = threadIdx.x; idx < H * D; idx += 256) {
        int h = idx >> 10, i = idx & (D - 1);
        us[h * 1028 + i] = g_u[idx];
    }
    __syncthreads();

    int h   = threadIdx.x & 15;
    int nl  = threadIdx.x >> 4;
    int row = blockIdx.x * 16 + nl;       // global (b,n) row, 0..65535
    int b   = row >> 11;
    int n   = row & (N - 1);

    const float4* zr = reinterpret_cast<const float4*>(z + (size_t)row * D);
    const float4* ur = reinterpret_cast<const float4*>(us + h * 1028);

    float a0 = 0.f, a1 = 0.f, a2 = 0.f, a3 = 0.f;
    #pragma unroll 8
    for (int i4 = 0; i4 < D / 4; i4++) {
        float4 zv = __ldg(&zr[i4]);
        float4 uv = ur[i4];
        a0 = fmaf(zv.x, uv.x, a0);
        a1 = fmaf(zv.y, uv.y, a1);
        a2 = fmaf(zv.z, uv.z, a2);
        a3 = fmaf(zv.w, uv.w, a3);
    }
    float s = (a0 + a1) + (a2 + a3) + g_c[h];
    bool valid = (g_maskb[b * N + n] != 0) || (n == 0 && g_force[b]);
    float neg_inf = __int_as_float(0xff800000);
    g_probs[((size_t)(b * H + h)) * N + n] = valid ? s : neg_inf;
}

// ---------------- K4: softmax over n (in place in g_probs) ------------------
__global__ void k_softmax() {
    __shared__ float smax[8], ssum[8];
    int bh = blockIdx.x;                        // 512 = B*H
    float* p = g_probs + (size_t)bh * N;
    int t = threadIdx.x, lane = t & 31, w = t >> 5;

    float v[8];
    float m = __int_as_float(0xff800000);
    #pragma unroll
    for (int k = 0; k < 8; k++) { v[k] = p[t + k * 256]; m = fmaxf(m, v[k]); }
    #pragma unroll
    for (int o = 16; o; o >>= 1) m = fmaxf(m, __shfl_xor_sync(0xffffffffu, m, o));
    if (lane == 0) smax[w] = m;
    __syncthreads();
    float mm = smax[0];
    #pragma unroll
    for (int k = 1; k < 8; k++) mm = fmaxf(mm, smax[k]);

    float s = 0.f;
    #pragma unroll
    for (int k = 0; k < 8; k++) { v[k] = __expf(v[k] - mm); s += v[k]; }
    s = warp_sum(s);
    if (lane == 0) ssum[w] = s;
    __syncthreads();
    float tot = ssum[0];
    #pragma unroll
    for (int k = 1; k < 8; k++) tot += ssum[k];
    float inv = 1.f / tot;
    #pragma unroll
    for (int k = 0; k < 8; k++) p[t + k * 256] = v[k] * inv;
}

// ---------------- K5: ctx[b,h,:] = sum_n p[b,h,n] * z[b,n,:] ----------------
// block = 256 threads = 16 float4-dims x 16 heads; 16 dim-tiles per batch.
// probs staged in smem [512][17] (padded, conflict-free). z float4 loads:
// 16 heads share each address -> z streamed from HBM exactly once (2nd pass).
__global__ void k_ctx(const float* __restrict__ z) {
    __shared__ float ps[512 * 17];
    int b   = blockIdx.x >> 4;
    int jt  = blockIdx.x & 15;
    int h   = threadIdx.x & 15;
    int i4l = threadIdx.x >> 4;      // 0..15
    int i4  = jt * 16 + i4l;         // float4 index within row, 0..255

    const float4* zb = reinterpret_cast<const float4*>(z) + (size_t)b * N * (D / 4);

    float4 acc = make_float4(0.f, 0.f, 0.f, 0.f);
    for (int n0 = 0; n0 < N; n0 += 512) {
        __syncthreads();
        for (int idx = threadIdx.x; idx < 512 * 16; idx += 256) {
            int hh = idx >> 9, nc = idx & 511;
            ps[nc * 17 + hh] = g_probs[((size_t)(b * H + hh)) * N + n0 + nc];
        }
        __syncthreads();
        #pragma unroll 4
        for (int nc = 0; nc < 512; nc++) {
            float pw = ps[nc * 17 + h];
            // skip fully-masked rows (all heads zero) -- warp-uniform check
            if (__ballot_sync(0xffffffffu, pw != 0.f)) {
                float4 zv = __ldg(&zb[(size_t)(n0 + nc) * (D / 4) + i4]);
                acc.x = fmaf(pw, zv.x, acc.x);
                acc.y = fmaf(pw, zv.y, acc.y);
                acc.z = fmaf(pw, zv.z, acc.z);
                acc.w = fmaf(pw, zv.w, acc.w);
            }
        }
    }
    *reinterpret_cast<float4*>(g_ctx + ((size_t)(b * H + h)) * D + i4 * 4) = acc;
}

// ---------------- K6: pooled[b,j] = w_v[j,:] . ctx[b,h(j),:] + b_v[j] -------
__global__ void k_pooled(const float* __restrict__ w_v, const float* __restrict__ b_v) {
    __shared__ float ws[8 * D];
    int j0 = blockIdx.x * 8;
    for (int idx = threadIdx.x; idx < 8 * D; idx += 256)
        ws[idx] = w_v[(size_t)j0 * D + idx];
    __syncthreads();

    int w = threadIdx.x >> 5, lane = threadIdx.x & 31;
    int j = j0 + w;
    int h = j >> 6;
    float bias = b_v[j];
    const float4* wr = reinterpret_cast<const float4*>(ws + w * D);
    for (int b = 0; b < B; b++) {
        const float4* cx = reinterpret_cast<const float4*>(g_ctx + ((size_t)(b * H + h)) * D);
        float acc = 0.f;
        #pragma unroll
        for (int i4 = lane; i4 < D / 4; i4 += 32) {
            float4 a = wr[i4];
            float4 c = __ldg(&cx[i4]);
            acc = fmaf(a.x, c.x, acc);
            acc = fmaf(a.y, c.y, acc);
            acc = fmaf(a.z, c.z, acc);
            acc = fmaf(a.w, c.w, acc);
        }
        acc = warp_sum(acc);
        if (lane == 0) g_pooled[b * D + j] = acc + bias;
    }
}

// ---------------- K7: out[b,j] = w_o[j,:] . pooled[b,:] + b_o[j] ------------
__global__ void k_out(const float* __restrict__ w_o, const float* __restrict__ b_o,
                      float* __restrict__ out) {
    __shared__ float ws[8 * D];
    int j0 = blockIdx.x * 8;
    for (int idx = threadIdx.x; idx < 8 * D; idx += 256)
        ws[idx] = w_o[(size_t)j0 * D + idx];
    __syncthreads();

    int w = threadIdx.x >> 5, lane = threadIdx.x & 31;
    int j = j0 + w;
    float bias = b_o[j];
    const float4* wr = reinterpret_cast<const float4*>(ws + w * D);
    for (int b = 0; b < B; b++) {
        const float4* px = reinterpret_cast<const float4*>(g_pooled + (size_t)b * D);
        float acc = 0.f;
        #pragma unroll
        for (int i4 = lane; i4 < D / 4; i4 += 32) {
            float4 a = wr[i4];
            float4 c = __ldg(&px[i4]);
            acc = fmaf(a.x, c.x, acc);
            acc = fmaf(a.y, c.y, acc);
            acc = fmaf(a.z, c.z, acc);
            acc = fmaf(a.w, c.w, acc);
        }
        acc = warp_sum(acc);
        if (lane == 0) out[b * D + j] = acc + bias;
    }
}

// ---------------- launch ----------------------------------------------------
extern "C" void kernel_launch(void* const* d_in, const int* in_sizes, int n_in,
                              void* d_out, int out_size) {
    const float* z     = (const float*)d_in[0];
    const void*  mask  = d_in[1];                 // dtype detected at runtime
    const float* query = (const float*)d_in[2];
    const float* w_q   = (const float*)d_in[3];
    const float* w_k   = (const float*)d_in[4];
    const float* w_v   = (const float*)d_in[5];
    const float* b_q   = (const float*)d_in[6];
    const float* b_k   = (const float*)d_in[7];
    const float* b_v   = (const float*)d_in[8];
    const float* w_o   = (const float*)d_in[9];
    const float* b_o   = (const float*)d_in[10];
    float*       out   = (float*)d_out;

    // u-cache needs 65792 B of dynamic smem (> 48KB default)
    cudaFuncSetAttribute(k_scores, cudaFuncAttributeMaxDynamicSharedMemorySize, 66048);

    k_maskprep<<<1, 1024>>>(mask);
    k_q       <<<128, 256>>>(query, w_q, b_q);
    k_u       <<<64, 256>>>(w_k);
    k_c       <<<1, 512>>>(b_k);
    k_scores  <<<(B * N) / 16, 256, 16 * 1028 * sizeof(float)>>>(z);
    k_softmax <<<B * H, 256>>>();
    k_ctx     <<<B * 16, 256>>>(z);
    k_pooled  <<<D / 8, 256>>>(w_v, b_v);
    k_out     <<<D / 8, 256>>>(w_o, b_o, out);
}

// round 10
// speedup vs baseline: 1.2529x; 1.2529x over previous
#include <cuda_runtime.h>
#include <cuda_bf16.h>
#include <cstddef>

// Problem constants
#define B 32
#define N 2048
#define D 1024
#define H 16
#define HD 64
#define SCALE 0.125f   // 1/sqrt(64)

// ---------------- scratch (device globals; no allocation allowed) -----------
__device__ float g_q[D];                 // q = query @ w_q.T + b_q
__device__ float g_u[H * D];             // u[h,i] = scale * sum_{j in head h} q[j]*w_k[j,i]
__device__ float g_c[H];                 // scale * q_h . b_k_h
__device__ int   g_force[B];             // 1 if row b has no valid key -> force n=0 valid
__device__ unsigned char g_maskb[B * N]; // canonicalized mask (1 = valid)
__device__ float g_probs[B * H * N];     // scores, then softmax probs (in place)
__device__ float g_ctx[B * H * D];       // ctx[b,h,:] = sum_n attn * z
__device__ float g_pooled[B * D];

typedef unsigned long long ull;

__device__ __forceinline__ float warp_sum(float v) {
    #pragma unroll
    for (int o = 16; o; o >>= 1) v += __shfl_xor_sync(0xffffffffu, v, o);
    return v;
}

// packed f32x2 helpers (Blackwell FFMA2 path — PTX-only)
__device__ __forceinline__ ull f2fma(ull a, ull b, ull c) {
    ull d;
    asm("fma.rn.f32x2 %0, %1, %2, %3;" : "=l"(d) : "l"(a), "l"(b), "l"(c));
    return d;
}
__device__ __forceinline__ ull f2add(ull a, ull b) {
    ull d;
    asm("add.rn.f32x2 %0, %1, %2;" : "=l"(d) : "l"(a), "l"(b));
    return d;
}
__device__ __forceinline__ ull pack2(float lo, float hi) {
    ull r;
    asm("mov.b64 %0, {%1, %2};" : "=l"(r) : "f"(lo), "f"(hi));
    return r;
}
__device__ __forceinline__ float2 unpack2(ull v) {
    float2 r;
    asm("mov.b64 {%0, %1}, %2;" : "=f"(r.x), "=f"(r.y) : "l"(v));
    return r;
}

// ---------------- K0: mask dtype detection + canonicalization + force -------
__global__ void k_maskprep(const void* __restrict__ mraw) {
    const unsigned int*   wrd = (const unsigned int*)mraw;
    const unsigned short* hlf = (const unsigned short*)mraw;
    const unsigned char*  byt = (const unsigned char*)mraw;

    __shared__ int bad_f32, bad_bf16, bad_i32, mode;
    int t = threadIdx.x;
    if (t == 0) { bad_f32 = 0; bad_bf16 = 0; bad_i32 = 0; }
    __syncthreads();

    int bf = 0, bb = 0, bi = 0;
    for (int i = t; i < (B * N) / 4; i += 1024) {   // 16384 words, in-bounds for all dtypes
        unsigned int x = wrd[i];
        if (x != 0u && x != 0x3F800000u) bf = 1;
        unsigned int lo = x & 0xFFFFu, hi = x >> 16;
        if ((lo != 0u && lo != 0x3F80u) || (hi != 0u && hi != 0x3F80u)) bb = 1;
        if (x > 1u) bi = 1;
    }
    if (bf) bad_f32 = 1;
    if (bb) bad_bf16 = 1;
    if (bi) bad_i32 = 1;
    __syncthreads();
    if (t == 0) mode = !bad_f32 ? 0 : (!bad_bf16 ? 1 : (!bad_i32 ? 2 : 3));
    __syncthreads();

    int m = mode;
    for (int i = t; i < B * N; i += 1024) {
        unsigned char v;
        if      (m == 0) v = (wrd[i] != 0u);   // float32 0.0 / 1.0
        else if (m == 1) v = (hlf[i] != 0);    // bf16
        else if (m == 2) v = (wrd[i] != 0u);   // int32
        else             v = (byt[i] != 0);    // bool bytes
        g_maskb[i] = v;
    }
    __syncthreads();

    int w = t >> 5, lane = t & 31;             // warp w handles batch w
    int found = 0;
    for (int n = lane; n < N; n += 32) found |= g_maskb[w * N + n];
    found = __ballot_sync(0xffffffffu, found);
    if (lane == 0) g_force[w] = (found == 0);
}

// ---------------- K1: q[j] = query . w_q[j,:] + b_q[j] ----------------------
__global__ void k_q(const float* __restrict__ query, const float* __restrict__ w_q,
                    const float* __restrict__ b_q) {
    int j    = (blockIdx.x * blockDim.x + threadIdx.x) >> 5;
    int lane = threadIdx.x & 31;
    if (j >= D) return;
    float acc = 0.f;
    const float* wr = w_q + (size_t)j * D;
    for (int i = lane; i < D; i += 32) acc = fmaf(query[i], wr[i], acc);
    acc = warp_sum(acc);
    if (lane == 0) g_q[j] = acc + b_q[j];
}

// ---------------- K2: u[h,i] (pre-scaled) -----------------------------------
__global__ void k_u(const float* __restrict__ w_k) {
    int t = blockIdx.x * 256 + threadIdx.x;   // 16384 threads
    int h = t >> 10;
    int i = t & (D - 1);
    float acc = 0.f;
    #pragma unroll 8
    for (int j = 0; j < HD; j++)
        acc = fmaf(g_q[h * HD + j], w_k[(size_t)(h * HD + j) * D + i], acc);
    g_u[t] = acc * SCALE;
}

// ---------------- K2c: c[h] = scale * q_h . b_k_h ---------------------------
__global__ void k_c(const float* __restrict__ b_k) {
    int h = threadIdx.x >> 5;
    int lane = threadIdx.x & 31;
    float acc = 0.f;
    for (int j = lane; j < HD; j += 32)
        acc = fmaf(g_q[h * HD + j], b_k[h * HD + j], acc);
    acc = warp_sum(acc);
    if (lane == 0) g_c[h] = acc * SCALE;
}

// ---------------- K3: scores + mask -----------------------------------------
// block = 256 threads = 16 heads x 16 slots; each thread computes R=8 rows for
// one head -> one u LDS.128 feeds 8 rows (LDS traffic /8, LDG MLP=8).
// u transposed in smem: us[i4][h][c] -> warp LDS.128 = 256B contiguous,
// conflict-free. z read as 16B vectors, shared by the 16 heads (broadcast);
// z streamed from HBM exactly once. FMA via packed f32x2 (2 FMA/instr).
#define RROWS 8
__global__ void __launch_bounds__(256) k_scores(const float* __restrict__ z) {
    extern __shared__ float us[];   // [256 i4][16 h][4 c] = 16384 floats = 64 KB
    for (int dst = threadIdx.x; dst < H * D; dst += 256) {
        int i4 = dst >> 6, h = (dst >> 2) & 15, c = dst & 3;
        us[dst] = g_u[h * D + i4 * 4 + c];
    }
    __syncthreads();

    int h    = threadIdx.x & 15;
    int slot = threadIdx.x >> 4;
    int row0 = blockIdx.x * 128 + slot * RROWS;   // 8 consecutive (b,n) rows
    int b    = row0 >> 11;                        // uniform per block (128 | 2048)
    int n0   = row0 & (N - 1);

    const ull* zr = reinterpret_cast<const ull*>(z + (size_t)row0 * D);  // 512 ull/row

    ull acc0[RROWS], acc1[RROWS];
    #pragma unroll
    for (int r = 0; r < RROWS; r++) { acc0[r] = 0ull; acc1[r] = 0ull; }

    #pragma unroll 2
    for (int i4 = 0; i4 < D / 4; i4++) {
        ull uv0 = *reinterpret_cast<const ull*>(us + i4 * 64 + h * 4);
        ull uv1 = *reinterpret_cast<const ull*>(us + i4 * 64 + h * 4 + 2);
        #pragma unroll
        for (int r = 0; r < RROWS; r++) {
            ull zv0 = __ldg(&zr[(size_t)r * 512 + i4 * 2]);
            ull zv1 = __ldg(&zr[(size_t)r * 512 + i4 * 2 + 1]);
            acc0[r] = f2fma(zv0, uv0, acc0[r]);
            acc1[r] = f2fma(zv1, uv1, acc1[r]);
        }
    }

    float ch = g_c[h];
    float neg_inf = __int_as_float(0xff800000);
    int   force   = g_force[b];
    float s[RROWS];
    #pragma unroll
    for (int r = 0; r < RROWS; r++) {
        float2 a = unpack2(acc0[r]);
        float2 c2 = unpack2(acc1[r]);
        float v = (a.x + a.y) + (c2.x + c2.y) + ch;
        int n = n0 + r;
        bool valid = (g_maskb[b * N + n] != 0) || (n == 0 && force);
        s[r] = valid ? v : neg_inf;
    }
    float4* pout = reinterpret_cast<float4*>(g_probs + ((size_t)(b * H + h)) * N + n0);
    pout[0] = make_float4(s[0], s[1], s[2], s[3]);
    pout[1] = make_float4(s[4], s[5], s[6], s[7]);
}

// ---------------- K4: softmax over n (in place in g_probs) ------------------
__global__ void k_softmax() {
    __shared__ float smax[8], ssum[8];
    int bh = blockIdx.x;                        // 512 = B*H
    float* p = g_probs + (size_t)bh * N;
    int t = threadIdx.x, lane = t & 31, w = t >> 5;

    float v[8];
    float m = __int_as_float(0xff800000);
    #pragma unroll
    for (int k = 0; k < 8; k++) { v[k] = p[t + k * 256]; m = fmaxf(m, v[k]); }
    #pragma unroll
    for (int o = 16; o; o >>= 1) m = fmaxf(m, __shfl_xor_sync(0xffffffffu, m, o));
    if (lane == 0) smax[w] = m;
    __syncthreads();
    float mm = smax[0];
    #pragma unroll
    for (int k = 1; k < 8; k++) mm = fmaxf(mm, smax[k]);

    float s = 0.f;
    #pragma unroll
    for (int k = 0; k < 8; k++) { v[k] = __expf(v[k] - mm); s += v[k]; }
    s = warp_sum(s);
    if (lane == 0) ssum[w] = s;
    __syncthreads();
    float tot = ssum[0];
    #pragma unroll
    for (int k = 1; k < 8; k++) tot += ssum[k];
    float inv = 1.f / tot;
    #pragma unroll
    for (int k = 0; k < 8; k++) p[t + k * 256] = v[k] * inv;
}

// ---------------- K5: ctx[b,h,:] = sum_n p[b,h,n] * z[b,n,:] ----------------
// block = 256 threads = 16 heads x 16 float4-dims; 16 dim-tiles per batch.
// probs staged in smem [512][17] (conflict-free). No ballot: masked probs are
// exactly 0.0 so the FMA is a no-op. Unroll 8 with even/odd accumulator pairs
// to break the FFMA RAW chain and batch 8 independent LDGs (MLP=8).
__global__ void __launch_bounds__(256) k_ctx(const float* __restrict__ z) {
    __shared__ float ps[512 * 17];
    int b   = blockIdx.x >> 4;
    int jt  = blockIdx.x & 15;
    int h   = threadIdx.x & 15;
    int i4l = threadIdx.x >> 4;      // 0..15
    int i4  = jt * 16 + i4l;         // float4 index within row, 0..255

    const ull* zq = reinterpret_cast<const ull*>(z) + (size_t)b * N * 512;

    ull a0e = 0ull, a1e = 0ull, a0o = 0ull, a1o = 0ull;
    for (int t0 = 0; t0 < N; t0 += 512) {
        __syncthreads();
        for (int idx = threadIdx.x; idx < 512 * 16; idx += 256) {
            int hh = idx >> 9, nc = idx & 511;
            ps[nc * 17 + hh] = g_probs[((size_t)(b * H + hh)) * N + t0 + nc];
        }
        __syncthreads();
        for (int nc = 0; nc < 512; nc += 8) {
            #pragma unroll
            for (int k = 0; k < 8; k++) {
                float pw = ps[(nc + k) * 17 + h];
                ull pp  = pack2(pw, pw);
                ull zv0 = __ldg(&zq[(size_t)(t0 + nc + k) * 512 + i4 * 2]);
                ull zv1 = __ldg(&zq[(size_t)(t0 + nc + k) * 512 + i4 * 2 + 1]);
                if (k & 1) { a0o = f2fma(pp, zv0, a0o); a1o = f2fma(pp, zv1, a1o); }
                else       { a0e = f2fma(pp, zv0, a0e); a1e = f2fma(pp, zv1, a1e); }
            }
        }
    }
    float2 r0 = unpack2(f2add(a0e, a0o));
    float2 r1 = unpack2(f2add(a1e, a1o));
    *reinterpret_cast<float4*>(g_ctx + ((size_t)(b * H + h)) * D + i4 * 4) =
        make_float4(r0.x, r0.y, r1.x, r1.y);
}

// ---------------- K6: pooled[b,j] = w_v[j,:] . ctx[b,h(j),:] + b_v[j] -------
__global__ void k_pooled(const float* __restrict__ w_v, const float* __restrict__ b_v) {
    __shared__ float ws[8 * D];
    int j0 = blockIdx.x * 8;
    for (int idx = threadIdx.x; idx < 8 * D; idx += 256)
        ws[idx] = w_v[(size_t)j0 * D + idx];
    __syncthreads();

    int w = threadIdx.x >> 5, lane = threadIdx.x & 31;
    int j = j0 + w;
    int h = j >> 6;
    float bias = b_v[j];
    const float4* wr = reinterpret_cast<const float4*>(ws + w * D);
    for (int b = 0; b < B; b++) {
        const float4* cx = reinterpret_cast<const float4*>(g_ctx + ((size_t)(b * H + h)) * D);
        float acc = 0.f;
        #pragma unroll
        for (int i4 = lane; i4 < D / 4; i4 += 32) {
            float4 a = wr[i4];
            float4 c = __ldg(&cx[i4]);
            acc = fmaf(a.x, c.x, acc);
            acc = fmaf(a.y, c.y, acc);
            acc = fmaf(a.z, c.z, acc);
            acc = fmaf(a.w, c.w, acc);
        }
        acc = warp_sum(acc);
        if (lane == 0) g_pooled[b * D + j] = acc + bias;
    }
}

// ---------------- K7: out[b,j] = w_o[j,:] . pooled[b,:] + b_o[j] ------------
__global__ void k_out(const float* __restrict__ w_o, const float* __restrict__ b_o,
                      float* __restrict__ out) {
    __shared__ float ws[8 * D];
    int j0 = blockIdx.x * 8;
    for (int idx = threadIdx.x; idx < 8 * D; idx += 256)
        ws[idx] = w_o[(size_t)j0 * D + idx];
    __syncthreads();

    int w = threadIdx.x >> 5, lane = threadIdx.x & 31;
    int j = j0 + w;
    float bias = b_o[j];
    const float4* wr = reinterpret_cast<const float4*>(ws + w * D);
    for (int b = 0; b < B; b++) {
        const float4* px = reinterpret_cast<const float4*>(g_pooled + (size_t)b * D);
        float acc = 0.f;
        #pragma unroll
        for (int i4 = lane; i4 < D / 4; i4 += 32) {
            float4 a = wr[i4];
            float4 c = __ldg(&px[i4]);
            acc = fmaf(a.x, c.x, acc);
            acc = fmaf(a.y, c.y, acc);
            acc = fmaf(a.z, c.z, acc);
            acc = fmaf(a.w, c.w, acc);
        }
        acc = warp_sum(acc);
        if (lane == 0) out[b * D + j] = acc + bias;
    }
}

// ---------------- launch ----------------------------------------------------
extern "C" void kernel_launch(void* const* d_in, const int* in_sizes, int n_in,
                              void* d_out, int out_size) {
    const float* z     = (const float*)d_in[0];
    const void*  mask  = d_in[1];                 // dtype detected at runtime
    const float* query = (const float*)d_in[2];
    const float* w_q   = (const float*)d_in[3];
    const float* w_k   = (const float*)d_in[4];
    const float* w_v   = (const float*)d_in[5];
    const float* b_q   = (const float*)d_in[6];
    const float* b_k   = (const float*)d_in[7];
    const float* b_v   = (const float*)d_in[8];
    const float* w_o   = (const float*)d_in[9];
    const float* b_o   = (const float*)d_in[10];
    float*       out   = (float*)d_out;

    // transposed u-cache: 64 KB dynamic smem (> 48KB default)
    cudaFuncSetAttribute(k_scores, cudaFuncAttributeMaxDynamicSharedMemorySize, 65536);

    k_maskprep<<<1, 1024>>>(mask);
    k_q       <<<128, 256>>>(query, w_q, b_q);
    k_u       <<<64, 256>>>(w_k);
    k_c       <<<1, 512>>>(b_k);
    k_scores  <<<(B * N) / 128, 256, 65536>>>(z);
    k_softmax <<<B * H, 256>>>();
    k_ctx     <<<B * 16, 256>>>(z);
    k_pooled  <<<D / 8, 256>>>(w_v, b_v);
    k_out     <<<D / 8, 256>>>(w_o, b_o, out);
}

// round 11
// speedup vs baseline: 3.4169x; 2.7272x over previous
#include <cuda_runtime.h>
#include <cuda_bf16.h>
#include <cstddef>

// Problem constants
#define B 32
#define N 2048
#define D 1024
#define H 16
#define HD 64
#define SCALE 0.125f   // 1/sqrt(64)
#define NSPLIT 8

// ---------------- scratch (device globals; no allocation allowed) -----------
__device__ float g_q[D];
__device__ float g_u[H * D];              // u[h,i] pre-scaled
__device__ float g_c[H];
__device__ int   g_force[B];
__device__ unsigned char g_maskb[B * N];
__device__ float g_probs[B * H * N];      // scores -> probs in place
__device__ float g_ctxp[NSPLIT * B * H * D]; // partial ctx per n-split (16 MB)
__device__ float g_ctx[B * H * D];
__device__ float g_pooled[B * D];

typedef unsigned long long ull;

__device__ __forceinline__ float warp_sum(float v) {
    #pragma unroll
    for (int o = 16; o; o >>= 1) v += __shfl_xor_sync(0xffffffffu, v, o);
    return v;
}
__device__ __forceinline__ ull f2fma(ull a, ull b, ull c) {
    ull d; asm("fma.rn.f32x2 %0, %1, %2, %3;" : "=l"(d) : "l"(a), "l"(b), "l"(c)); return d;
}
__device__ __forceinline__ ull f2add(ull a, ull b) {
    ull d; asm("add.rn.f32x2 %0, %1, %2;" : "=l"(d) : "l"(a), "l"(b)); return d;
}
__device__ __forceinline__ ull pack2(float lo, float hi) {
    ull r; asm("mov.b64 %0, {%1, %2};" : "=l"(r) : "f"(lo), "f"(hi)); return r;
}
__device__ __forceinline__ float2 unpack2(ull v) {
    float2 r; asm("mov.b64 {%0, %1}, %2;" : "=f"(r.x), "=f"(r.y) : "l"(v)); return r;
}

// ---------------- K0: mask dtype detection + canonicalization + force -------
__global__ void k_maskprep(const void* __restrict__ mraw) {
    const unsigned int*   wrd = (const unsigned int*)mraw;
    const unsigned short* hlf = (const unsigned short*)mraw;
    const unsigned char*  byt = (const unsigned char*)mraw;

    __shared__ int bad_f32, bad_bf16, bad_i32, mode;
    int t = threadIdx.x;
    if (t == 0) { bad_f32 = 0; bad_bf16 = 0; bad_i32 = 0; }
    __syncthreads();

    int bf = 0, bb = 0, bi = 0;
    for (int i = t; i < (B * N) / 4; i += 1024) {
        unsigned int x = wrd[i];
        if (x != 0u && x != 0x3F800000u) bf = 1;
        unsigned int lo = x & 0xFFFFu, hi = x >> 16;
        if ((lo != 0u && lo != 0x3F80u) || (hi != 0u && hi != 0x3F80u)) bb = 1;
        if (x > 1u) bi = 1;
    }
    if (bf) bad_f32 = 1;
    if (bb) bad_bf16 = 1;
    if (bi) bad_i32 = 1;
    __syncthreads();
    if (t == 0) mode = !bad_f32 ? 0 : (!bad_bf16 ? 1 : (!bad_i32 ? 2 : 3));
    __syncthreads();

    int m = mode;
    for (int i = t; i < B * N; i += 1024) {
        unsigned char v;
        if      (m == 0) v = (wrd[i] != 0u);
        else if (m == 1) v = (hlf[i] != 0);
        else if (m == 2) v = (wrd[i] != 0u);
        else             v = (byt[i] != 0);
        g_maskb[i] = v;
    }
    __syncthreads();

    int w = t >> 5, lane = t & 31;
    int found = 0;
    for (int n = lane; n < N; n += 32) found |= g_maskb[w * N + n];
    found = __ballot_sync(0xffffffffu, found);
    if (lane == 0) g_force[w] = (found == 0);
}

// ---------------- K1: q = query @ w_q.T + b_q --------------------------------
__global__ void k_q(const float* __restrict__ query, const float* __restrict__ w_q,
                    const float* __restrict__ b_q) {
    int j    = (blockIdx.x * blockDim.x + threadIdx.x) >> 5;
    int lane = threadIdx.x & 31;
    if (j >= D) return;
    float acc = 0.f;
    const float* wr = w_q + (size_t)j * D;
    for (int i = lane; i < D; i += 32) acc = fmaf(query[i], wr[i], acc);
    acc = warp_sum(acc);
    if (lane == 0) g_q[j] = acc + b_q[j];
}

// ---------------- K2: u[h,i] (pre-scaled) ------------------------------------
__global__ void k_u(const float* __restrict__ w_k) {
    int t = blockIdx.x * 256 + threadIdx.x;
    int h = t >> 10;
    int i = t & (D - 1);
    float acc = 0.f;
    #pragma unroll 8
    for (int j = 0; j < HD; j++)
        acc = fmaf(g_q[h * HD + j], w_k[(size_t)(h * HD + j) * D + i], acc);
    g_u[t] = acc * SCALE;
}

// ---------------- K2c: c[h] ---------------------------------------------------
__global__ void k_c(const float* __restrict__ b_k) {
    int h = threadIdx.x >> 5;
    int lane = threadIdx.x & 31;
    float acc = 0.f;
    for (int j = lane; j < HD; j += 32)
        acc = fmaf(g_q[h * HD + j], b_k[h * HD + j], acc);
    acc = warp_sum(acc);
    if (lane == 0) g_c[h] = acc * SCALE;
}

// ---------------- K3: scores --------------------------------------------------
// thread = (rg, s): rows rg*4..+3, i-slice {c*32 + s*4 ..+3}; ALL 8 head-pairs
// in f32x2 registers. z: direct gmem LDG.128, lanes (4 rg x 8 s) cover 128B per
// row -> fully coalesced, no smem, no syncs, MLP=8. u: smem stride-18 pairs
// (8B aligned, <=2-way conflict), one read amortized over 4 rows. i-partials
// reduced across the 8 s-lanes via 3x shfl.xor on packed accumulators.
__global__ void __launch_bounds__(256, 2) k_scores(const float* __restrict__ z) {
    extern __shared__ float us[];   // [1024][18]
    for (int idx = threadIdx.x; idx < H * D; idx += 256) {
        int h = idx >> 10, i = idx & (D - 1);
        us[i * 18 + h] = g_u[idx];
    }
    __syncthreads();

    int s    = threadIdx.x & 7;
    int rg   = threadIdx.x >> 3;               // 0..31
    int row0 = blockIdx.x * 128 + rg * 4;      // block covers 128 rows of one b
    int b    = row0 >> 11;
    const float* zbase = z + (size_t)row0 * D;

    ull acc[4][8];
    #pragma unroll
    for (int r = 0; r < 4; r++)
        #pragma unroll
        for (int hp = 0; hp < 8; hp++) acc[r][hp] = 0ull;

    #pragma unroll 2
    for (int c = 0; c < 32; c++) {
        int ib = c * 32 + s * 4;
        float za[4][4];
        #pragma unroll
        for (int r = 0; r < 4; r++)
            *reinterpret_cast<float4*>(za[r]) =
                __ldg(reinterpret_cast<const float4*>(zbase + (size_t)r * D + ib));
        #pragma unroll
        for (int ii = 0; ii < 4; ii++) {
            const ull* urow = reinterpret_cast<const ull*>(us + (size_t)(ib + ii) * 18);
            ull zz[4];
            #pragma unroll
            for (int r = 0; r < 4; r++) zz[r] = pack2(za[r][ii], za[r][ii]);
            #pragma unroll
            for (int hp = 0; hp < 8; hp++) {
                ull uv = urow[hp];
                #pragma unroll
                for (int r = 0; r < 4; r++)
                    acc[r][hp] = f2fma(zz[r], uv, acc[r][hp]);
            }
        }
    }

    // reduce over the 8 s-lanes (lane bits 0..2)
    #pragma unroll
    for (int r = 0; r < 4; r++)
        #pragma unroll
        for (int hp = 0; hp < 8; hp++) {
            ull v = acc[r][hp];
            #pragma unroll
            for (int o = 1; o <= 4; o <<= 1)
                v = f2add(v, __shfl_xor_sync(0xffffffffu, v, o));
            acc[r][hp] = v;
        }

    // lane s writes head pair hp == s (static indexing via predicated unroll)
    float neg_inf = __int_as_float(0xff800000);
    int   force   = g_force[b];
    #pragma unroll
    for (int hp = 0; hp < 8; hp++) if (hp == s) {
        float ch0 = g_c[2 * hp], ch1 = g_c[2 * hp + 1];
        #pragma unroll
        for (int r = 0; r < 4; r++) {
            int n = (row0 + r) & (N - 1);
            bool valid = (g_maskb[b * N + n] != 0) || (n == 0 && force);
            float2 v = unpack2(acc[r][hp]);
            float s0 = valid ? v.x + ch0 : neg_inf;
            float s1 = valid ? v.y + ch1 : neg_inf;
            g_probs[((size_t)(b * H + 2 * hp)) * N + n]     = s0;
            g_probs[((size_t)(b * H + 2 * hp + 1)) * N + n] = s1;
        }
    }
}

// ---------------- K4: softmax over n (in place) ------------------------------
__global__ void k_softmax() {
    __shared__ float smax[8], ssum[8];
    int bh = blockIdx.x;
    float* p = g_probs + (size_t)bh * N;
    int t = threadIdx.x, lane = t & 31, w = t >> 5;

    float v[8];
    float m = __int_as_float(0xff800000);
    #pragma unroll
    for (int k = 0; k < 8; k++) { v[k] = p[t + k * 256]; m = fmaxf(m, v[k]); }
    #pragma unroll
    for (int o = 16; o; o >>= 1) m = fmaxf(m, __shfl_xor_sync(0xffffffffu, m, o));
    if (lane == 0) smax[w] = m;
    __syncthreads();
    float mm = smax[0];
    #pragma unroll
    for (int k = 1; k < 8; k++) mm = fmaxf(mm, smax[k]);

    float s = 0.f;
    #pragma unroll
    for (int k = 0; k < 8; k++) { v[k] = __expf(v[k] - mm); s += v[k]; }
    s = warp_sum(s);
    if (lane == 0) ssum[w] = s;
    __syncthreads();
    float tot = ssum[0];
    #pragma unroll
    for (int k = 1; k < 8; k++) tot += ssum[k];
    float inv = 1.f / tot;
    #pragma unroll
    for (int k = 0; k < 8; k++) p[t + k * 256] = v[k] * inv;
}

// ---------------- K5: partial ctx over an n-split ----------------------------
// thread = float4 i-slice (coalesced z LDG.128), ALL 16 heads in f32x2 regs.
// probs broadcast from smem. Masked probs are exactly 0 -> FMA no-op, no branch.
__global__ void __launch_bounds__(256) k_ctx(const float* __restrict__ z) {
    __shared__ float ps[256 * 18];
    int b  = blockIdx.x >> 3;
    int ns = blockIdx.x & 7;
    int n0 = ns * (N / NSPLIT);            // 256 rows of n
    int i0 = threadIdx.x * 4;

    for (int idx = threadIdx.x; idx < 256 * H; idx += 256) {
        int nc = idx & 255, h = idx >> 8;
        ps[nc * 18 + h] = g_probs[((size_t)(b * H + h)) * N + n0 + nc];
    }
    __syncthreads();

    const float* zb = z + (size_t)b * N * D;

    ull acc[4][8];
    #pragma unroll
    for (int ii = 0; ii < 4; ii++)
        #pragma unroll
        for (int hp = 0; hp < 8; hp++) acc[ii][hp] = 0ull;

    #pragma unroll 2
    for (int nc = 0; nc < 256; nc++) {
        float za[4];
        *reinterpret_cast<float4*>(za) =
            __ldg(reinterpret_cast<const float4*>(zb + (size_t)(n0 + nc) * D + i0));
        ull zz[4];
        #pragma unroll
        for (int ii = 0; ii < 4; ii++) zz[ii] = pack2(za[ii], za[ii]);
        const ull* pp = reinterpret_cast<const ull*>(ps + nc * 18);
        #pragma unroll
        for (int hp = 0; hp < 8; hp++) {
            ull pv = pp[hp];
            #pragma unroll
            for (int ii = 0; ii < 4; ii++)
                acc[ii][hp] = f2fma(pv, zz[ii], acc[ii][hp]);
        }
    }

    float* dst = g_ctxp + (size_t)ns * (B * H * D) + (size_t)b * H * D;
    #pragma unroll
    for (int hp = 0; hp < 8; hp++)
        #pragma unroll
        for (int ii = 0; ii < 4; ii++) {
            float2 v = unpack2(acc[ii][hp]);
            dst[(size_t)(2 * hp) * D + i0 + ii]     = v.x;
            dst[(size_t)(2 * hp + 1) * D + i0 + ii] = v.y;
        }
}

// ---------------- K5b: reduce the NSPLIT partials (deterministic) ------------
__global__ void k_ctxred() {
    int x = blockIdx.x * 256 + threadIdx.x;     // float4 index, 131072 total
    const float4* src = reinterpret_cast<const float4*>(g_ctxp);
    float4 a = src[x];
    #pragma unroll
    for (int ns = 1; ns < NSPLIT; ns++) {
        float4 v = src[(size_t)ns * (B * H * D / 4) + x];
        a.x += v.x; a.y += v.y; a.z += v.z; a.w += v.w;
    }
    reinterpret_cast<float4*>(g_ctx)[x] = a;
}

// ---------------- K6: pooled[b,j] = w_v[j,:] . ctx[b,h(j),:] + b_v[j] --------
__global__ void k_pooled(const float* __restrict__ w_v, const float* __restrict__ b_v) {
    __shared__ float ws[8 * D];
    int j0 = blockIdx.x * 8;
    for (int idx = threadIdx.x; idx < 8 * D; idx += 256)
        ws[idx] = w_v[(size_t)j0 * D + idx];
    __syncthreads();

    int w = threadIdx.x >> 5, lane = threadIdx.x & 31;
    int j = j0 + w;
    int h = j >> 6;
    float bias = b_v[j];
    const float4* wr = reinterpret_cast<const float4*>(ws + w * D);
    for (int b = 0; b < B; b++) {
        const float4* cx = reinterpret_cast<const float4*>(g_ctx + ((size_t)(b * H + h)) * D);
        float acc = 0.f;
        #pragma unroll
        for (int i4 = lane; i4 < D / 4; i4 += 32) {
            float4 a = wr[i4];
            float4 c = __ldg(&cx[i4]);
            acc = fmaf(a.x, c.x, acc);
            acc = fmaf(a.y, c.y, acc);
            acc = fmaf(a.z, c.z, acc);
            acc = fmaf(a.w, c.w, acc);
        }
        acc = warp_sum(acc);
        if (lane == 0) g_pooled[b * D + j] = acc + bias;
    }
}

// ---------------- K7: out[b,j] = w_o[j,:] . pooled[b,:] + b_o[j] -------------
__global__ void k_out(const float* __restrict__ w_o, const float* __restrict__ b_o,
                      float* __restrict__ out) {
    __shared__ float ws[8 * D];
    int j0 = blockIdx.x * 8;
    for (int idx = threadIdx.x; idx < 8 * D; idx += 256)
        ws[idx] = w_o[(size_t)j0 * D + idx];
    __syncthreads();

    int w = threadIdx.x >> 5, lane = threadIdx.x & 31;
    int j = j0 + w;
    float bias = b_o[j];
    const float4* wr = reinterpret_cast<const float4*>(ws + w * D);
    for (int b = 0; b < B; b++) {
        const float4* px = reinterpret_cast<const float4*>(g_pooled + (size_t)b * D);
        float acc = 0.f;
        #pragma unroll
        for (int i4 = lane; i4 < D / 4; i4 += 32) {
            float4 a = wr[i4];
            float4 c = __ldg(&px[i4]);
            acc = fmaf(a.x, c.x, acc);
            acc = fmaf(a.y, c.y, acc);
            acc = fmaf(a.z, c.z, acc);
            acc = fmaf(a.w, c.w, acc);
        }
        acc = warp_sum(acc);
        if (lane == 0) out[b * D + j] = acc + bias;
    }
}

// ---------------- launch ------------------------------------------------------
extern "C" void kernel_launch(void* const* d_in, const int* in_sizes, int n_in,
                              void* d_out, int out_size) {
    const float* z     = (const float*)d_in[0];
    const void*  mask  = d_in[1];
    const float* query = (const float*)d_in[2];
    const float* w_q   = (const float*)d_in[3];
    const float* w_k   = (const float*)d_in[4];
    const float* w_v   = (const float*)d_in[5];
    const float* b_q   = (const float*)d_in[6];
    const float* b_k   = (const float*)d_in[7];
    const float* b_v   = (const float*)d_in[8];
    const float* w_o   = (const float*)d_in[9];
    const float* b_o   = (const float*)d_in[10];
    float*       out   = (float*)d_out;

    // u smem: 1024*18*4 = 73728 B
    cudaFuncSetAttribute(k_scores, cudaFuncAttributeMaxDynamicSharedMemorySize, 73728);

    k_maskprep<<<1, 1024>>>(mask);
    k_q       <<<128, 256>>>(query, w_q, b_q);
    k_u       <<<64, 256>>>(w_k);
    k_c       <<<1, 512>>>(b_k);
    k_scores  <<<(B * N) / 128, 256, 73728>>>(z);
    k_softmax <<<B * H, 256>>>();
    k_ctx     <<<B * NSPLIT, 256>>>(z);
    k_ctxred  <<<(B * H * D / 4) / 256, 256>>>();
    k_pooled  <<<D / 8, 256>>>(w_v, b_v);
    k_out     <<<D / 8, 256>>>(w_o, b_o, out);
}